// round 14
// baseline (speedup 1.0000x reference)
#include <cuda_runtime.h>
#include <cstdint>

#define B_ 8
#define L_ 8192
#define D_ 256

__device__ float g_kvsT[B_ * D_ * D_];  // [b][d][m]
__device__ float g_ksum[B_ * D_];       // [b][m]
__device__ int g_dummy;

__device__ __forceinline__ float relu_eps(float x) { return fmaxf(x, 0.0f) + 1e-3f; }
__device__ __forceinline__ uint32_t pack_f16(float lo, float hi) {
    uint32_t r;
    asm("cvt.rn.f16x2.f32 %0, %1, %2;" : "=r"(r) : "f"(hi), "f"(lo));
    return r;
}
__device__ __forceinline__ uint32_t smem_u32(const void* p) {
    uint32_t a;
    asm("{ .reg .u64 t; cvta.to.shared.u64 t, %1; cvt.u32.u64 %0, t; }" : "=r"(a) : "l"(p));
    return a;
}
__device__ __forceinline__ void cpa16(uint32_t s, const void* g) {
    asm volatile("cp.async.cg.shared.global [%0], [%1], 16;" :: "r"(s), "l"(g));
}
#define CP_COMMIT() asm volatile("cp.async.commit_group;" ::: "memory")
#define CP_WAIT1()  asm volatile("cp.async.wait_group 1;" ::: "memory")
#define CP_WAIT0()  asm volatile("cp.async.wait_group 0;" ::: "memory")

// m16n8k16 f16 MMA, fp32 accum.
__device__ __forceinline__ void mma16(float* c, const uint32_t* a, const uint32_t* b) {
    asm volatile("mma.sync.aligned.m16n8k16.row.col.f32.f16.f16.f32 "
        "{%0,%1,%2,%3}, {%4,%5,%6,%7}, {%8,%9}, {%0,%1,%2,%3};"
        : "+f"(c[0]), "+f"(c[1]), "+f"(c[2]), "+f"(c[3])
        : "r"(a[0]), "r"(a[1]), "r"(a[2]), "r"(a[3]), "r"(b[0]), "r"(b[1]));
}

#define TSTR 132   // pass1 [32 l][128m] tiles: phase bank 8t+g -> conflict-free
#define QSTR 40    // pass2 [128][32 k] tiles: LDS.64 phase bank 8g+2t -> conflict-free

// ---------------------------------------------------------------------------
__global__ void dummy_kernel() { if (threadIdx.x == 0) g_dummy = 0; }

__global__ void zero_kernel() {
    int i = blockIdx.x * 256 + threadIdx.x;
    float4 z = {0.f, 0.f, 0.f, 0.f};
    if (i < B_ * D_ * D_ / 4) ((float4*)g_kvsT)[i] = z;
    if (i < B_ * D_ / 4) ((float4*)g_ksum)[i] = z;
}

// ---------------------------------------------------------------------------
// Pass 1: kvsT[b][d][m] += sum_l relu'(K[l][m]) * V[l][d]   (+ fused ksum)
// grid (4 = 2m x 2d, 16 lchunks, B) = 512 CTAs, 128 thr (4 warps 2x2,
// warp tile 64m x 64d), K=512/CTA. __launch_bounds__(128,3) -> 3 CTAs/SM.
#define P1_SMEM (4 * 32 * TSTR * 4)

__global__ void __launch_bounds__(128, 3) pass1_mma(const float* __restrict__ K,
                                                    const float* __restrict__ V) {
    extern __shared__ float sm[];
    const int t = threadIdx.x, lane = t & 31, w = t >> 5;
    const int g = lane >> 2, tg = lane & 3;
    const int m0 = (blockIdx.x & 1) * 128, d0 = (blockIdx.x >> 1) * 128;
    const int b = blockIdx.z;
    const int lbase = blockIdx.y * 512;
    const int wm = (w & 1) * 64, wd = (w >> 1) * 64;
    const bool do_ksum = ((blockIdx.x >> 1) == 0) && ((w >> 1) == 0);

    float acc[4][8][4] = {};
    float ksA[4][2] = {};

    const uint32_t sb = smem_u32(sm);
    const float* Kg = K + (size_t)b * L_ * D_ + m0;
    const float* Vg = V + (size_t)b * L_ * D_ + d0;

    auto prefetch = [&](int s) {
        int buf = s & 1;
        uint32_t kb = sb + (uint32_t)(buf * 32 * TSTR) * 4;
        uint32_t vb = sb + (uint32_t)((2 + buf) * 32 * TSTR) * 4;
        const float* kg = Kg + (size_t)(lbase + s * 32) * D_;
        const float* vg = Vg + (size_t)(lbase + s * 32) * D_;
#pragma unroll
        for (int i = 0; i < 8; i++) {
            int j = t + i * 128, row = j >> 5, c = j & 31;
            uint32_t off = (uint32_t)(row * TSTR + c * 4) * 4;
            cpa16(kb + off, kg + (size_t)row * D_ + c * 4);
            cpa16(vb + off, vg + (size_t)row * D_ + c * 4);
        }
        CP_COMMIT();
    };

    prefetch(0);
    prefetch(1);

    const int S = 16;
    for (int s = 0; s < S; s++) {
        int buf = s & 1;
        if (s >= S - 2) { CP_WAIT0(); } else { CP_WAIT1(); }
        __syncthreads();
        const float* Kb = sm + buf * 32 * TSTR;
        const float* Vb = sm + (2 + buf) * 32 * TSTR;
#pragma unroll
        for (int kk = 0; kk < 2; kk++) {
            int r0 = (kk * 16 + 2 * tg) * TSTR;
            int r1 = r0 + TSTR;
            int r8 = r0 + 8 * TSTR;
            int r9 = r8 + TSTR;
            uint32_t Au[4][4];
#pragma unroll
            for (int mi = 0; mi < 4; mi++) {
                int col = wm + mi * 16 + g;
                float ka0 = relu_eps(Kb[r0 + col]),     ka1 = relu_eps(Kb[r1 + col]);
                float kb0 = relu_eps(Kb[r0 + col + 8]), kb1 = relu_eps(Kb[r1 + col + 8]);
                float kc0 = relu_eps(Kb[r8 + col]),     kc1 = relu_eps(Kb[r9 + col]);
                float kd0 = relu_eps(Kb[r8 + col + 8]), kd1 = relu_eps(Kb[r9 + col + 8]);
                ksA[mi][0] += (ka0 + ka1) + (kc0 + kc1);
                ksA[mi][1] += (kb0 + kb1) + (kd0 + kd1);
                Au[mi][0] = pack_f16(ka0, ka1);
                Au[mi][1] = pack_f16(kb0, kb1);
                Au[mi][2] = pack_f16(kc0, kc1);
                Au[mi][3] = pack_f16(kd0, kd1);
            }
            uint32_t Bf[8][2];
#pragma unroll
            for (int ni = 0; ni < 8; ni++) {
                int cn = wd + ni * 8 + g;
                Bf[ni][0] = pack_f16(Vb[r0 + cn], Vb[r1 + cn]);
                Bf[ni][1] = pack_f16(Vb[r8 + cn], Vb[r9 + cn]);
            }
#pragma unroll
            for (int mi = 0; mi < 4; mi++)
#pragma unroll
                for (int ni = 0; ni < 8; ni++) mma16(acc[mi][ni], Au[mi], Bf[ni]);
        }
        __syncthreads();
        if (s + 2 < S) prefetch(s + 2);
    }

    if (do_ksum) {
#pragma unroll
        for (int mi = 0; mi < 4; mi++) {
            float r0 = ksA[mi][0], r1 = ksA[mi][1];
            r0 += __shfl_xor_sync(0xffffffffu, r0, 1);
            r0 += __shfl_xor_sync(0xffffffffu, r0, 2);
            r1 += __shfl_xor_sync(0xffffffffu, r1, 1);
            r1 += __shfl_xor_sync(0xffffffffu, r1, 2);
            if (tg == 0) {
                atomicAdd(&g_ksum[b * D_ + m0 + wm + mi * 16 + g], r0);
                atomicAdd(&g_ksum[b * D_ + m0 + wm + mi * 16 + g + 8], r1);
            }
        }
    }

    float* base = &g_kvsT[(size_t)b * D_ * D_];
#pragma unroll
    for (int mi = 0; mi < 4; mi++) {
        int mrow = m0 + wm + mi * 16 + g;
#pragma unroll
        for (int ni = 0; ni < 8; ni++) {
            int dc = d0 + wd + ni * 8 + 2 * tg;
            atomicAdd(base + (size_t)dc * D_ + mrow, acc[mi][ni][0]);
            atomicAdd(base + (size_t)(dc + 1) * D_ + mrow, acc[mi][ni][1]);
            atomicAdd(base + (size_t)dc * D_ + mrow + 8, acc[mi][ni][2]);
            atomicAdd(base + (size_t)(dc + 1) * D_ + mrow + 8, acc[mi][ni][3]);
        }
    }
}

// ---------------------------------------------------------------------------
// Pass 2: out[l][d] = (sum_m q'[l][m] * kvsT[d][m]) / (sum_m q'[l][m] * ksum[m])
// grid (64 ltiles, 2 dtiles, B), 128 thr (4 warps 2x2, warp tile 64l x 64d).
#define KSOFF (4 * 128 * QSTR)
#define P2_SMEM ((KSOFF + 256) * 4)

__global__ void __launch_bounds__(128) pass2_mma(const float* __restrict__ Q,
                                                 float* __restrict__ out) {
    extern __shared__ float sm[];
    const int t = threadIdx.x, lane = t & 31, w = t >> 5;
    const int g = lane >> 2, tg = lane & 3;
    const int b = blockIdx.z;
    const int l0 = blockIdx.x * 128, d0 = blockIdx.y * 128;
    const int wl = (w & 1) * 64, wd = (w >> 1) * 64;
    float* ksum_s = sm + KSOFF;

    float acc[4][8][4] = {};
    float nA[4] = {}, nB[4] = {};

    const uint32_t sb = smem_u32(sm);
    const float* Qg = Q + ((size_t)b * L_ + l0) * D_;
    const float* KVg = g_kvsT + ((size_t)b * D_ + d0) * D_;
    const float* ksg = g_ksum + b * D_;

    auto prefetch = [&](int s) {
        int buf = s & 1;
        uint32_t qb = sb + (uint32_t)(buf * 128 * QSTR) * 4;
        uint32_t kb = sb + (uint32_t)((2 + buf) * 128 * QSTR) * 4;
        int mb = s * 32;
#pragma unroll
        for (int i = 0; i < 8; i++) {
            int j = t + i * 128, row = j >> 3, c = j & 7;
            uint32_t off = (uint32_t)(row * QSTR + c * 4) * 4;
            cpa16(qb + off, Qg + (size_t)row * D_ + mb + c * 4);
            cpa16(kb + off, KVg + (size_t)row * D_ + mb + c * 4);
        }
        CP_COMMIT();
    };

    // stage ksum into smem once
    ksum_s[t] = ksg[t];
    ksum_s[t + 128] = ksg[t + 128];

    prefetch(0);
    prefetch(1);

    const int S = 8;
    for (int s = 0; s < S; s++) {
        int buf = s & 1;
        if (s >= S - 2) { CP_WAIT0(); } else { CP_WAIT1(); }
        __syncthreads();
        const float* Qb = sm + buf * 128 * QSTR;
        const float* Kb = sm + (2 + buf) * 128 * QSTR;
        int mb = s * 32;
#pragma unroll
        for (int kk = 0; kk < 2; kk++) {
            int lo = kk * 16 + 2 * tg;
            float2 ks0 = *(const float2*)&ksum_s[mb + lo];
            float2 ks8 = *(const float2*)&ksum_s[mb + lo + 8];
            uint32_t Au[4][4];
#pragma unroll
            for (int mi = 0; mi < 4; mi++) {
                int rA = (wl + mi * 16 + g) * QSTR;
                int rB = rA + 8 * QSTR;
                float2 qa0 = *(const float2*)&Qb[rA + lo];
                float2 qa8 = *(const float2*)&Qb[rA + lo + 8];
                float2 qb0 = *(const float2*)&Qb[rB + lo];
                float2 qb8 = *(const float2*)&Qb[rB + lo + 8];
                float a00 = relu_eps(qa0.x), a01 = relu_eps(qa0.y);
                float a80 = relu_eps(qa8.x), a81 = relu_eps(qa8.y);
                float b00 = relu_eps(qb0.x), b01 = relu_eps(qb0.y);
                float b80 = relu_eps(qb8.x), b81 = relu_eps(qb8.y);
                nA[mi] += a00 * ks0.x + a01 * ks0.y + a80 * ks8.x + a81 * ks8.y;
                nB[mi] += b00 * ks0.x + b01 * ks0.y + b80 * ks8.x + b81 * ks8.y;
                Au[mi][0] = pack_f16(a00, a01);
                Au[mi][1] = pack_f16(b00, b01);
                Au[mi][2] = pack_f16(a80, a81);
                Au[mi][3] = pack_f16(b80, b81);
            }
            uint32_t Bf[8][2];
#pragma unroll
            for (int ni = 0; ni < 8; ni++) {
                int dn = (wd + ni * 8 + g) * QSTR;
                float2 v0 = *(const float2*)&Kb[dn + lo];
                float2 v8 = *(const float2*)&Kb[dn + lo + 8];
                Bf[ni][0] = pack_f16(v0.x, v0.y);
                Bf[ni][1] = pack_f16(v8.x, v8.y);
            }
#pragma unroll
            for (int mi = 0; mi < 4; mi++)
#pragma unroll
                for (int ni = 0; ni < 8; ni++) mma16(acc[mi][ni], Au[mi], Bf[ni]);
        }
        __syncthreads();
        if (s + 2 < S) prefetch(s + 2);
    }

#pragma unroll
    for (int mi = 0; mi < 4; mi++) {
        float r0 = nA[mi], r1 = nB[mi];
        r0 += __shfl_xor_sync(0xffffffffu, r0, 1);
        r0 += __shfl_xor_sync(0xffffffffu, r0, 2);
        r1 += __shfl_xor_sync(0xffffffffu, r1, 1);
        r1 += __shfl_xor_sync(0xffffffffu, r1, 2);
        float inv0 = 1.0f / r0, inv1 = 1.0f / r1;
        int lr = l0 + wl + mi * 16 + g;
#pragma unroll
        for (int ni = 0; ni < 8; ni++) {
            int dc = d0 + wd + ni * 8 + 2 * tg;
            float2 v0 = {acc[mi][ni][0] * inv0, acc[mi][ni][1] * inv0};
            float2 v1 = {acc[mi][ni][2] * inv1, acc[mi][ni][3] * inv1};
            *(float2*)&out[((size_t)b * L_ + lr) * D_ + dc] = v0;
            *(float2*)&out[((size_t)b * L_ + lr + 8) * D_ + dc] = v1;
        }
    }
}

// ---------------------------------------------------------------------------
extern "C" void kernel_launch(void* const* d_in, const int* in_sizes, int n_in,
                              void* d_out, int out_size) {
    const float* queries = (const float*)d_in[0];
    const float* keys    = (const float*)d_in[1];
    const float* values  = (const float*)d_in[2];
    float* out = (float*)d_out;

    cudaFuncSetAttribute(pass1_mma, cudaFuncAttributeMaxDynamicSharedMemorySize, P1_SMEM);
    cudaFuncSetAttribute(pass2_mma, cudaFuncAttributeMaxDynamicSharedMemorySize, P2_SMEM);

    // Keep profiler slot (launch index 3) on pass1_mma.
    dummy_kernel<<<1, 32>>>();
    dummy_kernel<<<1, 32>>>();
    zero_kernel<<<(B_ * D_ * D_ / 4 + 255) / 256, 256>>>();
    pass1_mma<<<dim3(4, 16, B_), 128, P1_SMEM>>>(keys, values);
    pass2_mma<<<dim3(L_ / 128, 2, B_), 128, P2_SMEM>>>(queries, out);
}

// round 15
// speedup vs baseline: 1.0664x; 1.0664x over previous
#include <cuda_runtime.h>
#include <cstdint>

#define B_ 8
#define L_ 8192
#define D_ 256

__device__ float g_kvsT[B_ * D_ * D_];  // [b][d][m]
__device__ float g_ksum[B_ * D_];       // [b][m]
__device__ int g_dummy;

__device__ __forceinline__ float relu_eps(float x) { return fmaxf(x, 0.0f) + 1e-3f; }
__device__ __forceinline__ uint32_t pack_f16(float lo, float hi) {
    uint32_t r;
    asm("cvt.rn.f16x2.f32 %0, %1, %2;" : "=r"(r) : "f"(hi), "f"(lo));
    return r;
}
__device__ __forceinline__ uint32_t smem_u32(const void* p) {
    uint32_t a;
    asm("{ .reg .u64 t; cvta.to.shared.u64 t, %1; cvt.u32.u64 %0, t; }" : "=r"(a) : "l"(p));
    return a;
}
__device__ __forceinline__ void cpa16(uint32_t s, const void* g) {
    asm volatile("cp.async.cg.shared.global [%0], [%1], 16;" :: "r"(s), "l"(g));
}
#define CP_COMMIT() asm volatile("cp.async.commit_group;" ::: "memory")
#define CP_WAIT1()  asm volatile("cp.async.wait_group 1;" ::: "memory")
#define CP_WAIT0()  asm volatile("cp.async.wait_group 0;" ::: "memory")

// m16n8k16 f16 MMA, fp32 accum.
__device__ __forceinline__ void mma16(float* c, const uint32_t* a, const uint32_t* b) {
    asm volatile("mma.sync.aligned.m16n8k16.row.col.f32.f16.f16.f32 "
        "{%0,%1,%2,%3}, {%4,%5,%6,%7}, {%8,%9}, {%0,%1,%2,%3};"
        : "+f"(c[0]), "+f"(c[1]), "+f"(c[2]), "+f"(c[3])
        : "r"(a[0]), "r"(a[1]), "r"(a[2]), "r"(a[3]), "r"(b[0]), "r"(b[1]));
}
#define LDSM4T(r0, r1, r2, r3, a) \
    asm volatile("ldmatrix.sync.aligned.m8n8.x4.trans.shared.b16 {%0,%1,%2,%3}, [%4];" \
        : "=r"(r0), "=r"(r1), "=r"(r2), "=r"(r3) : "r"(a))
#define STS2(a, p0, p1) \
    asm volatile("st.shared.v2.u32 [%0], {%1,%2};" :: "r"(a), "r"(p0), "r"(p1))

#define TSTR 132     // pass1 fp32 staging [32 l][128] tiles
#define QSTR 40      // pass2 [128][32 k] tiles: LDS.64 conflict-free
#define PITCH16 272  // fp16 tile row pitch bytes (136 halves = 17 x 16B)
#define F32BYTES (4 * 32 * TSTR * 4)          // 67584
#define K16OFF F32BYTES                       // fp16 K tile (single buffer)
#define V16OFF (F32BYTES + 32 * PITCH16)      // fp16 V tile
#define P1_SMEM (F32BYTES + 2 * 32 * PITCH16) // 84992

// ---------------------------------------------------------------------------
__global__ void dummy_kernel() { if (threadIdx.x == 0) g_dummy = 0; }

__global__ void zero_kernel() {
    int i = blockIdx.x * 256 + threadIdx.x;
    float4 z = {0.f, 0.f, 0.f, 0.f};
    if (i < B_ * D_ * D_ / 4) ((float4*)g_kvsT)[i] = z;
    if (i < B_ * D_ / 4) ((float4*)g_ksum)[i] = z;
}

// ---------------------------------------------------------------------------
// Pass 1: kvsT[b][d][m] += sum_l relu'(K[l][m]) * V[l][d]   (+ fused ksum)
// grid (4 = 2m x 2d, 8 lchunks, B) = 256 CTAs, 128 thr (4 warps 2x2,
// warp tile 64m x 64d). Stage: cp.async fp32 -> own-chunk sweep converts to
// fp16 tiles (relu+cvt.rn, fused ksum) -> ldmatrix.x4.trans fragments.
__global__ void __launch_bounds__(128, 2) pass1_mma(const float* __restrict__ K,
                                                    const float* __restrict__ V) {
    extern __shared__ float sm[];
    const int t = threadIdx.x, lane = t & 31, w = t >> 5;
    const int g = lane >> 2, tg = lane & 3;
    const int m0 = (blockIdx.x & 1) * 128, d0 = (blockIdx.x >> 1) * 128;
    const int b = blockIdx.z;
    const int lbase = blockIdx.y * 1024;
    const int wm = (w & 1) * 64, wd = (w >> 1) * 64;
    const bool do_ksum = (blockIdx.x >> 1) == 0;

    float acc[4][8][4] = {};
    float4 ksa = {0.f, 0.f, 0.f, 0.f};  // columns m0 + (t&31)*4 .. +3

    const uint32_t sb = smem_u32(sm);
    const uint32_t aK16 = sb + K16OFF, aV16 = sb + V16OFF;
    const float* Kg = K + (size_t)b * L_ * D_ + m0;
    const float* Vg = V + (size_t)b * L_ * D_ + d0;

    // ldmatrix per-lane offsets
    const int la = ((lane >> 4) & 1) * 8 + (lane & 7);  // A: l offset
    const int ma = ((lane >> 3) & 1) * 8;               // A: m offset
    const int lb = ((lane >> 3) & 1) * 8 + (lane & 7);  // B: l offset
    const int db = ((lane >> 4) & 1) * 8;               // B: d offset

    auto prefetch = [&](int s) {
        int buf = s & 1;
        uint32_t kb = sb + (uint32_t)(buf * 32 * TSTR) * 4;
        uint32_t vb = sb + (uint32_t)((2 + buf) * 32 * TSTR) * 4;
        const float* kg = Kg + (size_t)(lbase + s * 32) * D_;
        const float* vg = Vg + (size_t)(lbase + s * 32) * D_;
#pragma unroll
        for (int i = 0; i < 8; i++) {
            int j = t + i * 128, row = j >> 5, c = j & 31;
            uint32_t off = (uint32_t)(row * TSTR + c * 4) * 4;
            cpa16(kb + off, kg + (size_t)row * D_ + c * 4);
            cpa16(vb + off, vg + (size_t)row * D_ + c * 4);
        }
        CP_COMMIT();
    };

    prefetch(0);
    prefetch(1);

    const int S = 32;
    for (int s = 0; s < S; s++) {
        int buf = s & 1;
        if (s >= S - 2) { CP_WAIT0(); } else { CP_WAIT1(); }
        // Sweep own fp32 chunks -> fp16 tiles (K: relu+ksum; V: plain cvt).
        const float* Kb = sm + buf * 32 * TSTR;
        const float* Vb = sm + (2 + buf) * 32 * TSTR;
#pragma unroll
        for (int i = 0; i < 8; i++) {
            int j = t + i * 128, row = j >> 5, c = j & 31;
            float4 kv = *(const float4*)&Kb[row * TSTR + c * 4];
            kv.x = relu_eps(kv.x); kv.y = relu_eps(kv.y);
            kv.z = relu_eps(kv.z); kv.w = relu_eps(kv.w);
            if (do_ksum) { ksa.x += kv.x; ksa.y += kv.y; ksa.z += kv.z; ksa.w += kv.w; }
            STS2(aK16 + (uint32_t)(row * PITCH16 + c * 8),
                 pack_f16(kv.x, kv.y), pack_f16(kv.z, kv.w));
            float4 vv = *(const float4*)&Vb[row * TSTR + c * 4];
            STS2(aV16 + (uint32_t)(row * PITCH16 + c * 8),
                 pack_f16(vv.x, vv.y), pack_f16(vv.z, vv.w));
        }
        __syncthreads();
        if (s + 2 < S) prefetch(s + 2);  // fp32 buf of s now free

        // Fragments via ldmatrix, MMAs.
#pragma unroll
        for (int kk = 0; kk < 2; kk++) {
            int kb16 = kk * 16;
            uint32_t Au[4][4];
#pragma unroll
            for (int mi = 0; mi < 4; mi++) {
                uint32_t a = aK16 + (uint32_t)((kb16 + la) * PITCH16 + (wm + mi * 16 + ma) * 2);
                LDSM4T(Au[mi][0], Au[mi][1], Au[mi][2], Au[mi][3], a);
            }
            uint32_t Bf[8][2];
#pragma unroll
            for (int nj = 0; nj < 4; nj++) {
                uint32_t a = aV16 + (uint32_t)((kb16 + lb) * PITCH16 + (wd + nj * 16 + db) * 2);
                LDSM4T(Bf[2 * nj][0], Bf[2 * nj][1], Bf[2 * nj + 1][0], Bf[2 * nj + 1][1], a);
            }
#pragma unroll
            for (int mi = 0; mi < 4; mi++)
#pragma unroll
                for (int ni = 0; ni < 8; ni++) mma16(acc[mi][ni], Au[mi], Bf[ni]);
        }
        __syncthreads();  // fp16 tiles free for next sweep
    }

    if (do_ksum) {
        float* kp = &g_ksum[b * D_ + m0 + (t & 31) * 4];
        atomicAdd(kp + 0, ksa.x); atomicAdd(kp + 1, ksa.y);
        atomicAdd(kp + 2, ksa.z); atomicAdd(kp + 3, ksa.w);
    }

    float* base = &g_kvsT[(size_t)b * D_ * D_];
#pragma unroll
    for (int mi = 0; mi < 4; mi++) {
        int mrow = m0 + wm + mi * 16 + g;
#pragma unroll
        for (int ni = 0; ni < 8; ni++) {
            int dc = d0 + wd + ni * 8 + 2 * tg;
            atomicAdd(base + (size_t)dc * D_ + mrow, acc[mi][ni][0]);
            atomicAdd(base + (size_t)(dc + 1) * D_ + mrow, acc[mi][ni][1]);
            atomicAdd(base + (size_t)dc * D_ + mrow + 8, acc[mi][ni][2]);
            atomicAdd(base + (size_t)(dc + 1) * D_ + mrow + 8, acc[mi][ni][3]);
        }
    }
}

// ---------------------------------------------------------------------------
// Pass 2: out[l][d] = (sum_m q'[l][m] * kvsT[d][m]) / (sum_m q'[l][m] * ksum[m])
// grid (64 ltiles, 2 dtiles, B), 128 thr (4 warps 2x2, warp tile 64l x 64d).
#define KSOFF (4 * 128 * QSTR)
#define P2_SMEM ((KSOFF + 256) * 4)

__global__ void __launch_bounds__(128) pass2_mma(const float* __restrict__ Q,
                                                 float* __restrict__ out) {
    extern __shared__ float sm[];
    const int t = threadIdx.x, lane = t & 31, w = t >> 5;
    const int g = lane >> 2, tg = lane & 3;
    const int b = blockIdx.z;
    const int l0 = blockIdx.x * 128, d0 = blockIdx.y * 128;
    const int wl = (w & 1) * 64, wd = (w >> 1) * 64;
    float* ksum_s = sm + KSOFF;

    float acc[4][8][4] = {};
    float nA[4] = {}, nB[4] = {};

    const uint32_t sb = smem_u32(sm);
    const float* Qg = Q + ((size_t)b * L_ + l0) * D_;
    const float* KVg = g_kvsT + ((size_t)b * D_ + d0) * D_;
    const float* ksg = g_ksum + b * D_;

    auto prefetch = [&](int s) {
        int buf = s & 1;
        uint32_t qb = sb + (uint32_t)(buf * 128 * QSTR) * 4;
        uint32_t kb = sb + (uint32_t)((2 + buf) * 128 * QSTR) * 4;
        int mb = s * 32;
#pragma unroll
        for (int i = 0; i < 8; i++) {
            int j = t + i * 128, row = j >> 3, c = j & 7;
            uint32_t off = (uint32_t)(row * QSTR + c * 4) * 4;
            cpa16(qb + off, Qg + (size_t)row * D_ + mb + c * 4);
            cpa16(kb + off, KVg + (size_t)row * D_ + mb + c * 4);
        }
        CP_COMMIT();
    };

    ksum_s[t] = ksg[t];
    ksum_s[t + 128] = ksg[t + 128];

    prefetch(0);
    prefetch(1);

    const int S = 8;
    for (int s = 0; s < S; s++) {
        int buf = s & 1;
        if (s >= S - 2) { CP_WAIT0(); } else { CP_WAIT1(); }
        __syncthreads();
        const float* Qb = sm + buf * 128 * QSTR;
        const float* Kb = sm + (2 + buf) * 128 * QSTR;
        int mb = s * 32;
#pragma unroll
        for (int kk = 0; kk < 2; kk++) {
            int lo = kk * 16 + 2 * tg;
            float2 ks0 = *(const float2*)&ksum_s[mb + lo];
            float2 ks8 = *(const float2*)&ksum_s[mb + lo + 8];
            uint32_t Au[4][4];
#pragma unroll
            for (int mi = 0; mi < 4; mi++) {
                int rA = (wl + mi * 16 + g) * QSTR;
                int rB = rA + 8 * QSTR;
                float2 qa0 = *(const float2*)&Qb[rA + lo];
                float2 qa8 = *(const float2*)&Qb[rA + lo + 8];
                float2 qb0 = *(const float2*)&Qb[rB + lo];
                float2 qb8 = *(const float2*)&Qb[rB + lo + 8];
                float a00 = relu_eps(qa0.x), a01 = relu_eps(qa0.y);
                float a80 = relu_eps(qa8.x), a81 = relu_eps(qa8.y);
                float b00 = relu_eps(qb0.x), b01 = relu_eps(qb0.y);
                float b80 = relu_eps(qb8.x), b81 = relu_eps(qb8.y);
                nA[mi] += a00 * ks0.x + a01 * ks0.y + a80 * ks8.x + a81 * ks8.y;
                nB[mi] += b00 * ks0.x + b01 * ks0.y + b80 * ks8.x + b81 * ks8.y;
                Au[mi][0] = pack_f16(a00, a01);
                Au[mi][1] = pack_f16(b00, b01);
                Au[mi][2] = pack_f16(a80, a81);
                Au[mi][3] = pack_f16(b80, b81);
            }
            uint32_t Bf[8][2];
#pragma unroll
            for (int ni = 0; ni < 8; ni++) {
                int dn = (wd + ni * 8 + g) * QSTR;
                float2 v0 = *(const float2*)&Kb[dn + lo];
                float2 v8 = *(const float2*)&Kb[dn + lo + 8];
                Bf[ni][0] = pack_f16(v0.x, v0.y);
                Bf[ni][1] = pack_f16(v8.x, v8.y);
            }
#pragma unroll
            for (int mi = 0; mi < 4; mi++)
#pragma unroll
                for (int ni = 0; ni < 8; ni++) mma16(acc[mi][ni], Au[mi], Bf[ni]);
        }
        __syncthreads();
        if (s + 2 < S) prefetch(s + 2);
    }

#pragma unroll
    for (int mi = 0; mi < 4; mi++) {
        float r0 = nA[mi], r1 = nB[mi];
        r0 += __shfl_xor_sync(0xffffffffu, r0, 1);
        r0 += __shfl_xor_sync(0xffffffffu, r0, 2);
        r1 += __shfl_xor_sync(0xffffffffu, r1, 1);
        r1 += __shfl_xor_sync(0xffffffffu, r1, 2);
        float inv0 = 1.0f / r0, inv1 = 1.0f / r1;
        int lr = l0 + wl + mi * 16 + g;
#pragma unroll
        for (int ni = 0; ni < 8; ni++) {
            int dc = d0 + wd + ni * 8 + 2 * tg;
            float2 v0 = {acc[mi][ni][0] * inv0, acc[mi][ni][1] * inv0};
            float2 v1 = {acc[mi][ni][2] * inv1, acc[mi][ni][3] * inv1};
            *(float2*)&out[((size_t)b * L_ + lr) * D_ + dc] = v0;
            *(float2*)&out[((size_t)b * L_ + lr + 8) * D_ + dc] = v1;
        }
    }
}

// ---------------------------------------------------------------------------
extern "C" void kernel_launch(void* const* d_in, const int* in_sizes, int n_in,
                              void* d_out, int out_size) {
    const float* queries = (const float*)d_in[0];
    const float* keys    = (const float*)d_in[1];
    const float* values  = (const float*)d_in[2];
    float* out = (float*)d_out;

    cudaFuncSetAttribute(pass1_mma, cudaFuncAttributeMaxDynamicSharedMemorySize, P1_SMEM);
    cudaFuncSetAttribute(pass2_mma, cudaFuncAttributeMaxDynamicSharedMemorySize, P2_SMEM);

    // Keep profiler slot (launch index 3) on pass1_mma.
    dummy_kernel<<<1, 32>>>();
    dummy_kernel<<<1, 32>>>();
    zero_kernel<<<(B_ * D_ * D_ / 4 + 255) / 256, 256>>>();
    pass1_mma<<<dim3(4, 8, B_), 128, P1_SMEM>>>(keys, values);
    pass2_mma<<<dim3(L_ / 128, 2, B_), 128, P2_SMEM>>>(queries, out);
}